// round 2
// baseline (speedup 1.0000x reference)
#include <cuda_runtime.h>
#include <math.h>

#define SLEN   2048
#define BATCH  2
#define DMODEL 1024
#define NHEAD  16
#define DHEAD  64

// Scratch (allocation-free rule: __device__ globals). 4 x 16 MB = 64 MB.
static __device__ float g_Q[(size_t)BATCH * NHEAD * SLEN * DHEAD];
static __device__ float g_K[(size_t)BATCH * NHEAD * SLEN * DHEAD];
static __device__ float g_V[(size_t)BATCH * NHEAD * SLEN * DHEAD];
static __device__ float g_X[(size_t)SLEN * BATCH * DMODEL];

// ---------------------------------------------------------------------------
// Projection GEMM: C[M=4096, N=1024] = X[M,1024] @ W[1024,1024] + bias
// mode 0: z in {0,1,2} selects (query,Wq,bq)->g_Q etc; output scattered to
//         (B,H,S,DH) layout. mode 1: X = g_X, W = W0, bias = B0, plain
//         row-major output into out_final.
// 128x128 tile, BK=8, 256 threads, 8x8 per thread (split-64 fragments).
// ---------------------------------------------------------------------------
__global__ __launch_bounds__(256) void proj_gemm_kernel(
    const float* __restrict__ X0, const float* __restrict__ X1, const float* __restrict__ X2,
    const float* __restrict__ W0, const float* __restrict__ W1, const float* __restrict__ W2,
    const float* __restrict__ B0, const float* __restrict__ B1, const float* __restrict__ B2,
    float* __restrict__ out_final, int mode)
{
    __shared__ __align__(16) float As[8][128];
    __shared__ __align__(16) float Bs[8][128];

    const int tid = threadIdx.x;
    const int z = blockIdx.z;

    const float* X;
    const float* W;
    const float* Bp;
    if (mode == 0) {
        X  = (z == 0) ? X0 : (z == 1) ? X1 : X2;
        W  = (z == 0) ? W0 : (z == 1) ? W1 : W2;
        Bp = (z == 0) ? B0 : (z == 1) ? B1 : B2;
    } else {
        X = g_X; W = W0; Bp = B0;
    }

    const int m0 = blockIdx.y * 128;
    const int n0 = blockIdx.x * 128;

    const int arow = tid >> 1;           // 0..127
    const int acol = (tid & 1) * 4;      // 0 or 4
    const int brow = tid >> 5;           // 0..7
    const int bcol = (tid & 31) * 4;     // 0..124

    const int ty = tid >> 4;             // 0..15
    const int tx = tid & 15;             // 0..15

    float acc[8][8];
    #pragma unroll
    for (int i = 0; i < 8; i++)
        #pragma unroll
        for (int j = 0; j < 8; j++) acc[i][j] = 0.f;

    for (int k0 = 0; k0 < DMODEL; k0 += 8) {
        float4 av = *(const float4*)(X + (size_t)(m0 + arow) * DMODEL + k0 + acol);
        float4 bv = *(const float4*)(W + (size_t)(k0 + brow) * DMODEL + n0 + bcol);
        __syncthreads();
        As[acol + 0][arow] = av.x;
        As[acol + 1][arow] = av.y;
        As[acol + 2][arow] = av.z;
        As[acol + 3][arow] = av.w;
        *(float4*)&Bs[brow][bcol] = bv;
        __syncthreads();

        #pragma unroll
        for (int k = 0; k < 8; k++) {
            float4 a0 = *(const float4*)&As[k][ty * 4];
            float4 a1 = *(const float4*)&As[k][ty * 4 + 64];
            float4 b0 = *(const float4*)&Bs[k][tx * 4];
            float4 b1 = *(const float4*)&Bs[k][tx * 4 + 64];
            float ar[8] = {a0.x, a0.y, a0.z, a0.w, a1.x, a1.y, a1.z, a1.w};
            float br[8] = {b0.x, b0.y, b0.z, b0.w, b1.x, b1.y, b1.z, b1.w};
            #pragma unroll
            for (int i = 0; i < 8; i++)
                #pragma unroll
                for (int j = 0; j < 8; j++)
                    acc[i][j] += ar[i] * br[j];
        }
    }

    const int ca = n0 + tx * 4;          // first 4-col group
    const int cb = n0 + 64 + tx * 4;     // second 4-col group
    float4 ba4 = *(const float4*)(Bp + ca);
    float4 bb4 = *(const float4*)(Bp + cb);

    if (mode == 0) {
        float* O = (z == 0) ? g_Q : (z == 1) ? g_K : g_V;
        const int ha = ca >> 6, dha = ca & 63;
        const int hb = cb >> 6, dhb = cb & 63;
        #pragma unroll
        for (int i = 0; i < 8; i++) {
            int rl = (i < 4) ? (ty * 4 + i) : (64 + ty * 4 + i - 4);
            int r = m0 + rl;
            int s = r >> 1, b = r & 1;   // r = s*BATCH + b, BATCH=2
            float4 va = make_float4(acc[i][0] + ba4.x, acc[i][1] + ba4.y,
                                    acc[i][2] + ba4.z, acc[i][3] + ba4.w);
            float4 vb = make_float4(acc[i][4] + bb4.x, acc[i][5] + bb4.y,
                                    acc[i][6] + bb4.z, acc[i][7] + bb4.w);
            *(float4*)(O + ((size_t)(b * NHEAD + ha) * SLEN + s) * DHEAD + dha) = va;
            *(float4*)(O + ((size_t)(b * NHEAD + hb) * SLEN + s) * DHEAD + dhb) = vb;
        }
    } else {
        #pragma unroll
        for (int i = 0; i < 8; i++) {
            int rl = (i < 4) ? (ty * 4 + i) : (64 + ty * 4 + i - 4);
            size_t r = (size_t)(m0 + rl);
            float4 va = make_float4(acc[i][0] + ba4.x, acc[i][1] + ba4.y,
                                    acc[i][2] + ba4.z, acc[i][3] + ba4.w);
            float4 vb = make_float4(acc[i][4] + bb4.x, acc[i][5] + bb4.y,
                                    acc[i][6] + bb4.z, acc[i][7] + bb4.w);
            *(float4*)(out_final + r * DMODEL + ca) = va;
            *(float4*)(out_final + r * DMODEL + cb) = vb;
        }
    }
}

// ---------------------------------------------------------------------------
// Causal flash attention, fp32. One block = 64 query rows of one (b,h).
// grid = (S/64, B*H) = (32, 32); 256 threads (16x16, 4x4 per thread).
// smem: Qs[k][i] transposed (16KB), KVs (K transposed then V, 16KB),
//       Ps[j][i] transposed with XOR swizzle (16KB). Total exactly 48KB.
// ---------------------------------------------------------------------------
__global__ __launch_bounds__(256) void attn_kernel()
{
    __shared__ __align__(16) float Qs[64 * 64];   // Qs[k*64 + i]
    __shared__ __align__(16) float KVs[64 * 64];  // K: [k*64+j]; V: [j*64+d]
    __shared__ __align__(16) float Ps[64 * 64];   // swizzled transposed P

    const int tid = threadIdx.x;
    const int qb = blockIdx.x;        // query block 0..31
    const int bh = blockIdx.y;        // b*NHEAD + h
    const int b = bh >> 4;
    const int h = bh & 15;

    const float* Qg = g_Q + (size_t)bh * SLEN * DHEAD;
    const float* Kg = g_K + (size_t)bh * SLEN * DHEAD;
    const float* Vg = g_V + (size_t)bh * SLEN * DHEAD;

    const int ty = tid >> 4;          // 0..15 -> rows ty*4..ty*4+3
    const int tx = tid & 15;          // 0..15 -> cols tx*4..tx*4+3

    // Load Q tile transposed: Qs[dh][i]
    {
        int row = tid & 63;
        int c0 = tid >> 6;            // 0..3
        const float* src = Qg + (size_t)(qb * 64 + row) * DHEAD;
        #pragma unroll
        for (int it = 0; it < 4; it++) {
            int col4 = c0 + it * 4;
            float4 v = *(const float4*)(src + col4 * 4);
            Qs[(col4 * 4 + 0) * 64 + row] = v.x;
            Qs[(col4 * 4 + 1) * 64 + row] = v.y;
            Qs[(col4 * 4 + 2) * 64 + row] = v.z;
            Qs[(col4 * 4 + 3) * 64 + row] = v.w;
        }
    }

    float o[4][4];
    float m[4], l[4];
    #pragma unroll
    for (int i = 0; i < 4; i++) {
        m[i] = -1e30f; l[i] = 0.f;
        #pragma unroll
        for (int j = 0; j < 4; j++) o[i][j] = 0.f;
    }

    for (int kb = 0; kb <= qb; kb++) {
        __syncthreads();  // prior PV reads of KVs done
        // Load K tile transposed: KVs[dh][j]
        {
            int row = tid & 63;
            int c0 = tid >> 6;
            const float* src = Kg + (size_t)(kb * 64 + row) * DHEAD;
            #pragma unroll
            for (int it = 0; it < 4; it++) {
                int col4 = c0 + it * 4;
                float4 v = *(const float4*)(src + col4 * 4);
                KVs[(col4 * 4 + 0) * 64 + row] = v.x;
                KVs[(col4 * 4 + 1) * 64 + row] = v.y;
                KVs[(col4 * 4 + 2) * 64 + row] = v.z;
                KVs[(col4 * 4 + 3) * 64 + row] = v.w;
            }
        }
        __syncthreads();

        // S = scale * Q K^T  (4x4 per thread)
        float c[4][4];
        #pragma unroll
        for (int i = 0; i < 4; i++)
            #pragma unroll
            for (int j = 0; j < 4; j++) c[i][j] = 0.f;

        #pragma unroll 8
        for (int k = 0; k < 64; k++) {
            float4 aq = *(const float4*)&Qs[k * 64 + ty * 4];
            float4 ak = *(const float4*)&KVs[k * 64 + tx * 4];
            float aqr[4] = {aq.x, aq.y, aq.z, aq.w};
            float akr[4] = {ak.x, ak.y, ak.z, ak.w};
            #pragma unroll
            for (int i = 0; i < 4; i++)
                #pragma unroll
                for (int j = 0; j < 4; j++)
                    c[i][j] += aqr[i] * akr[j];
        }
        #pragma unroll
        for (int i = 0; i < 4; i++)
            #pragma unroll
            for (int j = 0; j < 4; j++) c[i][j] *= 0.125f;  // 1/sqrt(64)

        if (kb == qb) {  // causal diagonal block
            #pragma unroll
            for (int ii = 0; ii < 4; ii++)
                #pragma unroll
                for (int jj = 0; jj < 4; jj++)
                    if (tx * 4 + jj > ty * 4 + ii) c[ii][jj] = -1e30f;
        }

        // Online softmax, row stats reduced across the 16 tx lanes (xor<16)
        #pragma unroll
        for (int ii = 0; ii < 4; ii++) {
            float rm = fmaxf(fmaxf(c[ii][0], c[ii][1]), fmaxf(c[ii][2], c[ii][3]));
            rm = fmaxf(rm, __shfl_xor_sync(0xffffffffu, rm, 1));
            rm = fmaxf(rm, __shfl_xor_sync(0xffffffffu, rm, 2));
            rm = fmaxf(rm, __shfl_xor_sync(0xffffffffu, rm, 4));
            rm = fmaxf(rm, __shfl_xor_sync(0xffffffffu, rm, 8));
            float mnew = fmaxf(m[ii], rm);
            float alpha = __expf(m[ii] - mnew);
            m[ii] = mnew;
            float rs = 0.f;
            #pragma unroll
            for (int jj = 0; jj < 4; jj++) {
                c[ii][jj] = __expf(c[ii][jj] - mnew);
                rs += c[ii][jj];
            }
            rs += __shfl_xor_sync(0xffffffffu, rs, 1);
            rs += __shfl_xor_sync(0xffffffffu, rs, 2);
            rs += __shfl_xor_sync(0xffffffffu, rs, 4);
            rs += __shfl_xor_sync(0xffffffffu, rs, 8);
            l[ii] = l[ii] * alpha + rs;
            #pragma unroll
            for (int jj = 0; jj < 4; jj++) o[ii][jj] *= alpha;
        }

        // Store P transposed with XOR swizzle: f4 slot = (i/4) ^ (j>>2)
        #pragma unroll
        for (int jj = 0; jj < 4; jj++) {
            int j = tx * 4 + jj;
            ((float4*)Ps)[j * 16 + (ty ^ tx)] =
                make_float4(c[0][jj], c[1][jj], c[2][jj], c[3][jj]);
        }
        __syncthreads();  // Ps visible; done reading K from KVs

        // Load V tile (row-major): KVs[j][d]
        {
            int row = tid >> 2;       // 0..63
            int c4 = tid & 3;         // 0..3
            const float* src = Vg + (size_t)(kb * 64 + row) * DHEAD;
            #pragma unroll
            for (int it = 0; it < 4; it++) {
                int col4 = c4 + it * 4;
                *(float4*)&KVs[row * 64 + col4 * 4] = *(const float4*)(src + col4 * 4);
            }
        }
        __syncthreads();

        // O += P @ V
        #pragma unroll 8
        for (int j = 0; j < 64; j++) {
            float4 pf = ((const float4*)Ps)[j * 16 + (ty ^ ((j >> 2) & 15))];
            float4 vf = *(const float4*)&KVs[j * 64 + tx * 4];
            float pr[4] = {pf.x, pf.y, pf.z, pf.w};
            float vr[4] = {vf.x, vf.y, vf.z, vf.w};
            #pragma unroll
            for (int ii = 0; ii < 4; ii++)
                #pragma unroll
                for (int jj = 0; jj < 4; jj++)
                    o[ii][jj] += pr[ii] * vr[jj];
        }
    }

    // Normalize and write to g_X in (S, B, H*DH) layout
    #pragma unroll
    for (int ii = 0; ii < 4; ii++) {
        int i = ty * 4 + ii;
        int s = qb * 64 + i;
        float inv = 1.f / l[ii];
        float4 w = make_float4(o[ii][0] * inv, o[ii][1] * inv,
                               o[ii][2] * inv, o[ii][3] * inv);
        *(float4*)(g_X + ((size_t)s * BATCH + b) * DMODEL + h * DHEAD + tx * 4) = w;
    }
}

// ---------------------------------------------------------------------------
// Inputs (metadata order): query, key, value, mask, Wq, bq, Wk, bk, Wv, bv,
// Wo, bo. mask is the fixed causal tril -> handled analytically, not read.
// ---------------------------------------------------------------------------
extern "C" void kernel_launch(void* const* d_in, const int* in_sizes, int n_in,
                              void* d_out, int out_size)
{
    (void)in_sizes; (void)n_in; (void)out_size;
    const float* query = (const float*)d_in[0];
    const float* key   = (const float*)d_in[1];
    const float* value = (const float*)d_in[2];
    const float* Wq = (const float*)d_in[4];
    const float* bq = (const float*)d_in[5];
    const float* Wk = (const float*)d_in[6];
    const float* bk = (const float*)d_in[7];
    const float* Wv = (const float*)d_in[8];
    const float* bv = (const float*)d_in[9];
    const float* Wo = (const float*)d_in[10];
    const float* bo = (const float*)d_in[11];
    float* out = (float*)d_out;

    dim3 blk(256);
    // QKV projections (z selects q/k/v)
    proj_gemm_kernel<<<dim3(8, 32, 3), blk>>>(query, key, value,
                                              Wq, Wk, Wv, bq, bk, bv,
                                              nullptr, 0);
    // Causal flash attention
    attn_kernel<<<dim3(32, 32), blk>>>();
    // Output projection -> d_out
    proj_gemm_kernel<<<dim3(8, 32, 1), blk>>>(nullptr, nullptr, nullptr,
                                              Wo, nullptr, nullptr,
                                              bo, nullptr, nullptr,
                                              out, 1);
}

// round 3
// speedup vs baseline: 1.8667x; 1.8667x over previous
#include <cuda_runtime.h>
#include <cuda_bf16.h>
#include <math.h>
#include <stdint.h>

#define SLEN   2048
#define BATCH  2
#define DMODEL 1024
#define NHEAD  16
#define DHEAD  64

// Scratch (allocation-free rule: __device__ globals).
static __device__ float g_Q[(size_t)BATCH * NHEAD * SLEN * DHEAD];
static __device__ float g_K[(size_t)BATCH * NHEAD * SLEN * DHEAD];
static __device__ float g_V[(size_t)BATCH * NHEAD * SLEN * DHEAD];
static __device__ float g_X[(size_t)SLEN * BATCH * DMODEL];

// ---------------------------------------------------------------------------
// MMA helpers
// ---------------------------------------------------------------------------
__device__ __forceinline__ uint32_t smem_u32(const void* p) {
    return (uint32_t)__cvta_generic_to_shared(p);
}
__device__ __forceinline__ void ldsm4(uint32_t& r0, uint32_t& r1, uint32_t& r2,
                                      uint32_t& r3, uint32_t a) {
    asm volatile("ldmatrix.sync.aligned.m8n8.x4.shared.b16 {%0,%1,%2,%3}, [%4];"
                 : "=r"(r0), "=r"(r1), "=r"(r2), "=r"(r3) : "r"(a));
}
__device__ __forceinline__ void ldsm4t(uint32_t& r0, uint32_t& r1, uint32_t& r2,
                                       uint32_t& r3, uint32_t a) {
    asm volatile("ldmatrix.sync.aligned.m8n8.x4.trans.shared.b16 {%0,%1,%2,%3}, [%4];"
                 : "=r"(r0), "=r"(r1), "=r"(r2), "=r"(r3) : "r"(a));
}
__device__ __forceinline__ void mma16816(float* d, const uint32_t* a, const uint32_t* b) {
    asm volatile("mma.sync.aligned.m16n8k16.row.col.f32.bf16.bf16.f32 "
                 "{%0,%1,%2,%3}, {%4,%5,%6,%7}, {%8,%9}, {%0,%1,%2,%3};"
                 : "+f"(d[0]), "+f"(d[1]), "+f"(d[2]), "+f"(d[3])
                 : "r"(a[0]), "r"(a[1]), "r"(a[2]), "r"(a[3]), "r"(b[0]), "r"(b[1]));
}
// Split fp32 pair into hi/lo bf16x2 packs (x in low half, y in high half).
__device__ __forceinline__ void hilo_pack(float x, float y, uint32_t& h, uint32_t& l) {
    __nv_bfloat16 hx = __float2bfloat16(x);
    __nv_bfloat16 hy = __float2bfloat16(y);
    __nv_bfloat16 lx = __float2bfloat16(x - __bfloat162float(hx));
    __nv_bfloat16 ly = __float2bfloat16(y - __bfloat162float(hy));
    __nv_bfloat162 hp = __halves2bfloat162(hx, hy);
    __nv_bfloat162 lp = __halves2bfloat162(lx, ly);
    h = *reinterpret_cast<uint32_t*>(&hp);
    l = *reinterpret_cast<uint32_t*>(&lp);
}

// ---------------------------------------------------------------------------
// Projection GEMM: C[4096,1024] = X @ W + bias, bf16 split 3-pass MMA.
// BM=128, BN=128, BK=32; 8 warps (2m x 4n); warp tile 64x32.
// mode 0: z picks q/k/v; scatter to (B,H,S,DH). mode 1: g_X @ Wo -> out.
// ---------------------------------------------------------------------------
#define PA 40    // A smem pitch (elems): 80B rows -> conflict-free, 16B-aligned
#define PB 136   // B smem pitch: 272B rows -> conflict-free, 16B-aligned

__global__ __launch_bounds__(256, 1) void proj_mma_kernel(
    const float* __restrict__ X0, const float* __restrict__ X1, const float* __restrict__ X2,
    const float* __restrict__ W0, const float* __restrict__ W1, const float* __restrict__ W2,
    const float* __restrict__ B0, const float* __restrict__ B1, const float* __restrict__ B2,
    float* __restrict__ out_final, int mode)
{
    __shared__ __nv_bfloat16 Ah[128 * PA], Al[128 * PA];
    __shared__ __nv_bfloat16 Bh[32 * PB],  Bl[32 * PB];

    const int tid  = threadIdx.x;
    const int lane = tid & 31;
    const int wid  = tid >> 5;
    const int wm   = wid >> 2;   // 0..1
    const int wn   = wid & 3;    // 0..3
    const int z    = blockIdx.z;

    const float *X, *W, *Bp;
    if (mode == 0) {
        X  = (z == 0) ? X0 : (z == 1) ? X1 : X2;
        W  = (z == 0) ? W0 : (z == 1) ? W1 : W2;
        Bp = (z == 0) ? B0 : (z == 1) ? B1 : B2;
    } else {
        X = g_X; W = W0; Bp = B0;
    }

    const int m0 = blockIdx.y * 128;
    const int n0 = blockIdx.x * 128;

    const int ar = tid >> 1;           // 0..127
    const int ac = (tid & 1) * 16;     // 0 / 16
    const int br = tid >> 3;           // 0..31
    const int bc = (tid & 7) * 16;     // 0..112

    float acc[4][4][4];
    #pragma unroll
    for (int mt = 0; mt < 4; mt++)
        #pragma unroll
        for (int nt = 0; nt < 4; nt++)
            #pragma unroll
            for (int i = 0; i < 4; i++) acc[mt][nt][i] = 0.f;

    for (int k0 = 0; k0 < DMODEL; k0 += 32) {
        float4 av[4], bv[4];
        #pragma unroll
        for (int i = 0; i < 4; i++) {
            av[i] = *(const float4*)(X + (size_t)(m0 + ar) * DMODEL + k0 + ac + 4 * i);
            bv[i] = *(const float4*)(W + (size_t)(k0 + br) * DMODEL + n0 + bc + 4 * i);
        }
        __syncthreads();
        #pragma unroll
        for (int i = 0; i < 4; i++) {
            uint32_t h, l;
            hilo_pack(av[i].x, av[i].y, h, l);
            *(uint32_t*)&Ah[ar * PA + ac + 4 * i]     = h;
            *(uint32_t*)&Al[ar * PA + ac + 4 * i]     = l;
            hilo_pack(av[i].z, av[i].w, h, l);
            *(uint32_t*)&Ah[ar * PA + ac + 4 * i + 2] = h;
            *(uint32_t*)&Al[ar * PA + ac + 4 * i + 2] = l;
            hilo_pack(bv[i].x, bv[i].y, h, l);
            *(uint32_t*)&Bh[br * PB + bc + 4 * i]     = h;
            *(uint32_t*)&Bl[br * PB + bc + 4 * i]     = l;
            hilo_pack(bv[i].z, bv[i].w, h, l);
            *(uint32_t*)&Bh[br * PB + bc + 4 * i + 2] = h;
            *(uint32_t*)&Bl[br * PB + bc + 4 * i + 2] = l;
        }
        __syncthreads();

        #pragma unroll
        for (int ks = 0; ks < 2; ks++) {
            uint32_t ah[4][4], al_[4][4];
            #pragma unroll
            for (int mt = 0; mt < 4; mt++) {
                int row = wm * 64 + mt * 16 + (lane & 15);
                int col = ks * 16 + (lane >> 4) * 8;
                ldsm4(ah[mt][0],  ah[mt][1],  ah[mt][2],  ah[mt][3],
                      smem_u32(&Ah[row * PA + col]));
                ldsm4(al_[mt][0], al_[mt][1], al_[mt][2], al_[mt][3],
                      smem_u32(&Al[row * PA + col]));
            }
            const int g = lane >> 3;
            #pragma unroll
            for (int p = 0; p < 2; p++) {
                int row = ks * 16 + (g & 1) * 8 + (lane & 7);
                int col = wn * 32 + p * 16 + (g >> 1) * 8;
                uint32_t h0, h1, h2, h3, l0, l1, l2, l3;
                ldsm4t(h0, h1, h2, h3, smem_u32(&Bh[row * PB + col]));
                ldsm4t(l0, l1, l2, l3, smem_u32(&Bl[row * PB + col]));
                uint32_t bh0[2] = {h0, h1}, bh1[2] = {h2, h3};
                uint32_t bl0[2] = {l0, l1}, bl1[2] = {l2, l3};
                #pragma unroll
                for (int mt = 0; mt < 4; mt++) {
                    mma16816(acc[mt][2 * p],     ah[mt],  bh0);
                    mma16816(acc[mt][2 * p],     ah[mt],  bl0);
                    mma16816(acc[mt][2 * p],     al_[mt], bh0);
                    mma16816(acc[mt][2 * p + 1], ah[mt],  bh1);
                    mma16816(acc[mt][2 * p + 1], ah[mt],  bl1);
                    mma16816(acc[mt][2 * p + 1], al_[mt], bh1);
                }
            }
        }
    }

    // Epilogue: bias + scatter
    const int r  = lane >> 2;
    const int cp = (lane & 3) * 2;
    #pragma unroll
    for (int nt = 0; nt < 4; nt++) {
        int col = n0 + wn * 32 + nt * 8 + cp;
        float2 bb = *(const float2*)(Bp + col);
        #pragma unroll
        for (int mt = 0; mt < 4; mt++) {
            #pragma unroll
            for (int half = 0; half < 2; half++) {
                int row = m0 + wm * 64 + mt * 16 + r + half * 8;
                float2 v = make_float2(acc[mt][nt][half * 2 + 0] + bb.x,
                                       acc[mt][nt][half * 2 + 1] + bb.y);
                if (mode == 0) {
                    float* O = (z == 0) ? g_Q : (z == 1) ? g_K : g_V;
                    int s = row >> 1, b = row & 1;
                    int hh = col >> 6, dh = col & 63;
                    *(float2*)(O + ((size_t)(b * NHEAD + hh) * SLEN + s) * DHEAD + dh) = v;
                } else {
                    *(float2*)(out_final + (size_t)row * DMODEL + col) = v;
                }
            }
        }
    }
}

// ---------------------------------------------------------------------------
// Causal flash attention, bf16 split 3-pass MMA. BM=128 q rows per block,
// BN=64 keys per iter. 8 warps x 16 rows; each warp spans full N ->
// softmax is warp-local. Q frags in registers; P frags built from S regs.
// ---------------------------------------------------------------------------
#define PK 72    // K/V smem pitch: 144B rows -> conflict-free, 16B-aligned

__global__ __launch_bounds__(256, 1) void attn_mma_kernel()
{
    __shared__ __nv_bfloat16 Kh[64 * PK], Kl[64 * PK];
    __shared__ __nv_bfloat16 Vh[64 * PK], Vl[64 * PK];

    const int tid  = threadIdx.x;
    const int lane = tid & 31;
    const int wid  = tid >> 5;
    const int qb   = gridDim.x - 1 - blockIdx.x;   // heavy blocks first
    const int bh   = blockIdx.y;
    const int b    = bh >> 4;
    const int h    = bh & 15;

    const float* Qg = g_Q + (size_t)bh * SLEN * DHEAD;
    const float* Kg = g_K + (size_t)bh * SLEN * DHEAD;
    const float* Vg = g_V + (size_t)bh * SLEN * DHEAD;

    const int r  = lane >> 2;
    const int cp = (lane & 3) * 2;
    const int q0 = qb * 128 + wid * 16;

    // Q fragments (hi/lo), built once from global
    uint32_t aqh[4][4], aql[4][4];
    #pragma unroll
    for (int ks = 0; ks < 4; ks++) {
        float2 v0 = *(const float2*)(Qg + (size_t)(q0 + r)     * DHEAD + ks * 16 + cp);
        float2 v1 = *(const float2*)(Qg + (size_t)(q0 + 8 + r) * DHEAD + ks * 16 + cp);
        float2 v2 = *(const float2*)(Qg + (size_t)(q0 + r)     * DHEAD + ks * 16 + 8 + cp);
        float2 v3 = *(const float2*)(Qg + (size_t)(q0 + 8 + r) * DHEAD + ks * 16 + 8 + cp);
        hilo_pack(v0.x, v0.y, aqh[ks][0], aql[ks][0]);
        hilo_pack(v1.x, v1.y, aqh[ks][1], aql[ks][1]);
        hilo_pack(v2.x, v2.y, aqh[ks][2], aql[ks][2]);
        hilo_pack(v3.x, v3.y, aqh[ks][3], aql[ks][3]);
    }

    float o[8][4];
    #pragma unroll
    for (int t = 0; t < 8; t++)
        #pragma unroll
        for (int i = 0; i < 4; i++) o[t][i] = 0.f;
    float mrow[2] = {-1e30f, -1e30f};
    float lrow[2] = {0.f, 0.f};

    const int lr = tid >> 2;          // loader row 0..63
    const int lc = (tid & 3) * 16;    // loader col base

    const int nkb = 2 * qb + 2;
    for (int kb = 0; kb < nkb; kb++) {
        float4 kv[4], vv[4];
        #pragma unroll
        for (int i = 0; i < 4; i++) {
            kv[i] = *(const float4*)(Kg + (size_t)(kb * 64 + lr) * DHEAD + lc + 4 * i);
            vv[i] = *(const float4*)(Vg + (size_t)(kb * 64 + lr) * DHEAD + lc + 4 * i);
        }
        __syncthreads();
        #pragma unroll
        for (int i = 0; i < 4; i++) {
            uint32_t hh, ll;
            hilo_pack(kv[i].x, kv[i].y, hh, ll);
            *(uint32_t*)&Kh[lr * PK + lc + 4 * i]     = hh;
            *(uint32_t*)&Kl[lr * PK + lc + 4 * i]     = ll;
            hilo_pack(kv[i].z, kv[i].w, hh, ll);
            *(uint32_t*)&Kh[lr * PK + lc + 4 * i + 2] = hh;
            *(uint32_t*)&Kl[lr * PK + lc + 4 * i + 2] = ll;
            hilo_pack(vv[i].x, vv[i].y, hh, ll);
            *(uint32_t*)&Vh[lr * PK + lc + 4 * i]     = hh;
            *(uint32_t*)&Vl[lr * PK + lc + 4 * i]     = ll;
            hilo_pack(vv[i].z, vv[i].w, hh, ll);
            *(uint32_t*)&Vh[lr * PK + lc + 4 * i + 2] = hh;
            *(uint32_t*)&Vl[lr * PK + lc + 4 * i + 2] = ll;
        }
        __syncthreads();

        // S = Q K^T (scaled later)
        float s[8][4];
        #pragma unroll
        for (int t = 0; t < 8; t++)
            #pragma unroll
            for (int i = 0; i < 4; i++) s[t][i] = 0.f;

        const int g = lane >> 3;
        #pragma unroll
        for (int ks = 0; ks < 4; ks++) {
            #pragma unroll
            for (int p = 0; p < 4; p++) {
                int row = p * 16 + (g >> 1) * 8 + (lane & 7);
                int col = ks * 16 + (g & 1) * 8;
                uint32_t h0, h1, h2, h3, l0, l1, l2, l3;
                ldsm4(h0, h1, h2, h3, smem_u32(&Kh[row * PK + col]));
                ldsm4(l0, l1, l2, l3, smem_u32(&Kl[row * PK + col]));
                uint32_t bh0[2] = {h0, h1}, bh1[2] = {h2, h3};
                uint32_t bl0[2] = {l0, l1}, bl1[2] = {l2, l3};
                mma16816(s[2 * p],     aqh[ks], bh0);
                mma16816(s[2 * p],     aqh[ks], bl0);
                mma16816(s[2 * p],     aql[ks], bh0);
                mma16816(s[2 * p + 1], aqh[ks], bh1);
                mma16816(s[2 * p + 1], aqh[ks], bl1);
                mma16816(s[2 * p + 1], aql[ks], bh1);
            }
        }

        #pragma unroll
        for (int t = 0; t < 8; t++)
            #pragma unroll
            for (int i = 0; i < 4; i++) s[t][i] *= 0.125f;   // 1/sqrt(64)

        if (kb >= 2 * qb) {   // causal diagonal region
            #pragma unroll
            for (int t = 0; t < 8; t++)
                #pragma unroll
                for (int i = 0; i < 4; i++) {
                    int jg = kb * 64 + t * 8 + cp + (i & 1);
                    int qg = q0 + r + (i >> 1) * 8;
                    if (jg > qg) s[t][i] = -1e30f;
                }
        }

        // Online softmax per half-row (r and r+8)
        #pragma unroll
        for (int hr = 0; hr < 2; hr++) {
            float rm = -1e30f;
            #pragma unroll
            for (int t = 0; t < 8; t++)
                rm = fmaxf(rm, fmaxf(s[t][hr * 2], s[t][hr * 2 + 1]));
            rm = fmaxf(rm, __shfl_xor_sync(0xffffffffu, rm, 1));
            rm = fmaxf(rm, __shfl_xor_sync(0xffffffffu, rm, 2));
            float mn = fmaxf(mrow[hr], rm);
            float alpha = __expf(mrow[hr] - mn);
            mrow[hr] = mn;
            float rs = 0.f;
            #pragma unroll
            for (int t = 0; t < 8; t++) {
                s[t][hr * 2]     = __expf(s[t][hr * 2] - mn);
                s[t][hr * 2 + 1] = __expf(s[t][hr * 2 + 1] - mn);
                rs += s[t][hr * 2] + s[t][hr * 2 + 1];
            }
            rs += __shfl_xor_sync(0xffffffffu, rs, 1);
            rs += __shfl_xor_sync(0xffffffffu, rs, 2);
            lrow[hr] = lrow[hr] * alpha + rs;
            #pragma unroll
            for (int t = 0; t < 8; t++) {
                o[t][hr * 2]     *= alpha;
                o[t][hr * 2 + 1] *= alpha;
            }
        }

        // O += P V  (P frags straight from S registers)
        #pragma unroll
        for (int ks = 0; ks < 4; ks++) {
            uint32_t pah[4], pal[4];
            hilo_pack(s[2 * ks][0],     s[2 * ks][1],     pah[0], pal[0]);
            hilo_pack(s[2 * ks][2],     s[2 * ks][3],     pah[1], pal[1]);
            hilo_pack(s[2 * ks + 1][0], s[2 * ks + 1][1], pah[2], pal[2]);
            hilo_pack(s[2 * ks + 1][2], s[2 * ks + 1][3], pah[3], pal[3]);
            #pragma unroll
            for (int p = 0; p < 4; p++) {
                int row = ks * 16 + (g & 1) * 8 + (lane & 7);
                int col = p * 16 + (g >> 1) * 8;
                uint32_t h0, h1, h2, h3, l0, l1, l2, l3;
                ldsm4t(h0, h1, h2, h3, smem_u32(&Vh[row * PK + col]));
                ldsm4t(l0, l1, l2, l3, smem_u32(&Vl[row * PK + col]));
                uint32_t bh0[2] = {h0, h1}, bh1[2] = {h2, h3};
                uint32_t bl0[2] = {l0, l1}, bl1[2] = {l2, l3};
                mma16816(o[2 * p],     pah, bh0);
                mma16816(o[2 * p],     pah, bl0);
                mma16816(o[2 * p],     pal, bh0);
                mma16816(o[2 * p + 1], pah, bh1);
                mma16816(o[2 * p + 1], pah, bl1);
                mma16816(o[2 * p + 1], pal, bh1);
            }
        }
    }

    // Normalize and write to g_X in (S, B, H*DH) layout
    float inv0 = 1.f / lrow[0];
    float inv1 = 1.f / lrow[1];
    #pragma unroll
    for (int t = 0; t < 8; t++) {
        int d = t * 8 + cp;
        int s0 = q0 + r, s1 = q0 + 8 + r;
        *(float2*)(g_X + ((size_t)s0 * BATCH + b) * DMODEL + h * DHEAD + d) =
            make_float2(o[t][0] * inv0, o[t][1] * inv0);
        *(float2*)(g_X + ((size_t)s1 * BATCH + b) * DMODEL + h * DHEAD + d) =
            make_float2(o[t][2] * inv1, o[t][3] * inv1);
    }
}

// ---------------------------------------------------------------------------
// Inputs (metadata order): query, key, value, mask, Wq, bq, Wk, bk, Wv, bv,
// Wo, bo. mask is the fixed causal tril -> handled analytically, not read.
// ---------------------------------------------------------------------------
extern "C" void kernel_launch(void* const* d_in, const int* in_sizes, int n_in,
                              void* d_out, int out_size)
{
    (void)in_sizes; (void)n_in; (void)out_size;
    const float* query = (const float*)d_in[0];
    const float* key   = (const float*)d_in[1];
    const float* value = (const float*)d_in[2];
    const float* Wq = (const float*)d_in[4];
    const float* bq = (const float*)d_in[5];
    const float* Wk = (const float*)d_in[6];
    const float* bk = (const float*)d_in[7];
    const float* Wv = (const float*)d_in[8];
    const float* bv = (const float*)d_in[9];
    const float* Wo = (const float*)d_in[10];
    const float* bo = (const float*)d_in[11];
    float* out = (float*)d_out;

    dim3 blk(256);
    proj_mma_kernel<<<dim3(8, 32, 3), blk>>>(query, key, value,
                                             Wq, Wk, Wv, bq, bk, bv,
                                             nullptr, 0);
    attn_mma_kernel<<<dim3(16, 32), blk>>>();
    proj_mma_kernel<<<dim3(8, 32, 1), blk>>>(nullptr, nullptr, nullptr,
                                             Wo, nullptr, nullptr,
                                             bo, nullptr, nullptr,
                                             out, 1);
}

// round 4
// speedup vs baseline: 2.4477x; 1.3112x over previous
#include <cuda_runtime.h>
#include <cuda_bf16.h>
#include <math.h>
#include <stdint.h>

#define SLEN   2048
#define BATCH  2
#define DMODEL 1024
#define NHEAD  16
#define DHEAD  64
#define NX ((size_t)SLEN * BATCH * DMODEL)   // 4194304
#define NW ((size_t)DMODEL * DMODEL)         // 1048576

// bf16 hi/lo copies of everything (allocation-free rule: __device__ globals)
static __device__ __nv_bfloat16 g_Xh[3][NX], g_Xl[3][NX];   // query,key,value
static __device__ __nv_bfloat16 g_Wh[4][NW], g_Wl[4][NW];   // Wq,Wk,Wv,Wo
static __device__ __nv_bfloat16 g_Qh[NX], g_Ql[NX];         // (B,H,S,DH)
static __device__ __nv_bfloat16 g_Kh2[NX], g_Kl2[NX];
static __device__ __nv_bfloat16 g_Vh2[NX], g_Vl2[NX];
static __device__ __nv_bfloat16 g_Ah[NX], g_Al[NX];         // attn out (S,B,D)

// ---------------------------------------------------------------------------
// Helpers
// ---------------------------------------------------------------------------
__device__ __forceinline__ uint32_t smem_u32(const void* p) {
    return (uint32_t)__cvta_generic_to_shared(p);
}
__device__ __forceinline__ void cp16(uint32_t s, const void* g) {
    asm volatile("cp.async.cg.shared.global [%0], [%1], 16;" :: "r"(s), "l"(g));
}
__device__ __forceinline__ void cp_commit() {
    asm volatile("cp.async.commit_group;");
}
__device__ __forceinline__ void cp_wait0() {
    asm volatile("cp.async.wait_group 0;" ::: "memory");
}
__device__ __forceinline__ void ldsm4(uint32_t& r0, uint32_t& r1, uint32_t& r2,
                                      uint32_t& r3, uint32_t a) {
    asm volatile("ldmatrix.sync.aligned.m8n8.x4.shared.b16 {%0,%1,%2,%3}, [%4];"
                 : "=r"(r0), "=r"(r1), "=r"(r2), "=r"(r3) : "r"(a));
}
__device__ __forceinline__ void ldsm4t(uint32_t& r0, uint32_t& r1, uint32_t& r2,
                                       uint32_t& r3, uint32_t a) {
    asm volatile("ldmatrix.sync.aligned.m8n8.x4.trans.shared.b16 {%0,%1,%2,%3}, [%4];"
                 : "=r"(r0), "=r"(r1), "=r"(r2), "=r"(r3) : "r"(a));
}
__device__ __forceinline__ void mma16816(float* d, const uint32_t* a, const uint32_t* b) {
    asm volatile("mma.sync.aligned.m16n8k16.row.col.f32.bf16.bf16.f32 "
                 "{%0,%1,%2,%3}, {%4,%5,%6,%7}, {%8,%9}, {%0,%1,%2,%3};"
                 : "+f"(d[0]), "+f"(d[1]), "+f"(d[2]), "+f"(d[3])
                 : "r"(a[0]), "r"(a[1]), "r"(a[2]), "r"(a[3]), "r"(b[0]), "r"(b[1]));
}
__device__ __forceinline__ void hilo_pack(float x, float y, uint32_t& h, uint32_t& l) {
    __nv_bfloat16 hx = __float2bfloat16(x);
    __nv_bfloat16 hy = __float2bfloat16(y);
    __nv_bfloat16 lx = __float2bfloat16(x - __bfloat162float(hx));
    __nv_bfloat16 ly = __float2bfloat16(y - __bfloat162float(hy));
    __nv_bfloat162 hp = __halves2bfloat162(hx, hy);
    __nv_bfloat162 lp = __halves2bfloat162(lx, ly);
    h = *reinterpret_cast<uint32_t*>(&hp);
    l = *reinterpret_cast<uint32_t*>(&lp);
}

// ---------------------------------------------------------------------------
// Prepass: fp32 -> hi/lo bf16 for the 3 inputs and 4 weights
// ---------------------------------------------------------------------------
__global__ __launch_bounds__(256) void convert_kernel(
    const float* __restrict__ q, const float* __restrict__ k, const float* __restrict__ v,
    const float* __restrict__ wq, const float* __restrict__ wk,
    const float* __restrict__ wv, const float* __restrict__ wo)
{
    const int z = blockIdx.z;
    const float* src;
    __nv_bfloat16 *dh, *dl;
    size_t n;
    switch (z) {
        case 0: src = q;  dh = g_Xh[0]; dl = g_Xl[0]; n = NX; break;
        case 1: src = k;  dh = g_Xh[1]; dl = g_Xl[1]; n = NX; break;
        case 2: src = v;  dh = g_Xh[2]; dl = g_Xl[2]; n = NX; break;
        case 3: src = wq; dh = g_Wh[0]; dl = g_Wl[0]; n = NW; break;
        case 4: src = wk; dh = g_Wh[1]; dl = g_Wl[1]; n = NW; break;
        case 5: src = wv; dh = g_Wh[2]; dl = g_Wl[2]; n = NW; break;
        default: src = wo; dh = g_Wh[3]; dl = g_Wl[3]; n = NW; break;
    }
    size_t i = ((size_t)blockIdx.x * 256 + threadIdx.x) * 4;
    if (i >= n) return;
    float4 val = *(const float4*)(src + i);
    uint32_t h0, l0, h1, l1;
    hilo_pack(val.x, val.y, h0, l0);
    hilo_pack(val.z, val.w, h1, l1);
    *(uint2*)(dh + i) = make_uint2(h0, h1);
    *(uint2*)(dl + i) = make_uint2(l0, l1);
}

// ---------------------------------------------------------------------------
// Projection GEMM: C[4096,1024] = X @ W + bias, 3-pass split-bf16 MMA.
// bf16 hi/lo inputs from globals; cp.async 2-stage pipeline; 1 barrier/iter.
// mode 0: z picks q/k/v; writes hi/lo bf16 scattered to (B,H,S,DH).
// mode 1: g_A @ Wo + bo -> fp32 out.
// ---------------------------------------------------------------------------
#define PA 40
#define PB 136
#define A_BYTES (128 * PA * 2)                 // 10240
#define B_BYTES (32 * PB * 2)                  // 8704
#define STAGE_P (2 * A_BYTES + 2 * B_BYTES)    // 37888

__global__ __launch_bounds__(256, 1) void proj_mma_kernel(
    const float* __restrict__ Bias0, const float* __restrict__ Bias1,
    const float* __restrict__ Bias2, float* __restrict__ out_final, int mode)
{
    extern __shared__ char sm[];
    const int tid  = threadIdx.x;
    const int lane = tid & 31;
    const int wid  = tid >> 5;
    const int wm   = wid >> 2;
    const int wn   = wid & 3;
    const int z    = blockIdx.z;

    const __nv_bfloat16 *Agh, *Agl, *Wgh, *Wgl;
    const float* Bp;
    if (mode == 0) {
        Agh = g_Xh[z]; Agl = g_Xl[z]; Wgh = g_Wh[z]; Wgl = g_Wl[z];
        Bp = (z == 0) ? Bias0 : (z == 1) ? Bias1 : Bias2;
    } else {
        Agh = g_Ah; Agl = g_Al; Wgh = g_Wh[3]; Wgl = g_Wl[3];
        Bp = Bias0;
    }

    const int m0 = blockIdx.y * 128;
    const int n0 = blockIdx.x * 128;

    const int a_row = tid >> 1, a_bc = (tid & 1) * 2;
    const int b_row = tid >> 3, b_bc = (tid & 7) * 2;

    auto issue = [&](int stg, int k0) {
        char* s = sm + stg * STAGE_P;
        #pragma unroll
        for (int j = 0; j < 2; j++) {
            int ch = a_bc + j;
            uint32_t sa = smem_u32(s + a_row * 80 + ch * 16);
            const __nv_bfloat16* gh = Agh + (size_t)(m0 + a_row) * DMODEL + k0 + ch * 8;
            const __nv_bfloat16* gl = Agl + (size_t)(m0 + a_row) * DMODEL + k0 + ch * 8;
            cp16(sa, gh);
            cp16(sa + A_BYTES, gl);
        }
        #pragma unroll
        for (int j = 0; j < 2; j++) {
            int ch = b_bc + j;
            uint32_t sb = smem_u32(s + 2 * A_BYTES + b_row * 272 + ch * 16);
            const __nv_bfloat16* gh = Wgh + (size_t)(k0 + b_row) * DMODEL + n0 + ch * 8;
            const __nv_bfloat16* gl = Wgl + (size_t)(k0 + b_row) * DMODEL + n0 + ch * 8;
            cp16(sb, gh);
            cp16(sb + B_BYTES, gl);
        }
    };

    float acc[4][4][4];
    #pragma unroll
    for (int mt = 0; mt < 4; mt++)
        #pragma unroll
        for (int nt = 0; nt < 4; nt++)
            #pragma unroll
            for (int i = 0; i < 4; i++) acc[mt][nt][i] = 0.f;

    issue(0, 0);
    cp_commit();

    for (int it = 0; it < DMODEL / 32; it++) {
        cp_wait0();
        __syncthreads();
        if (it + 1 < DMODEL / 32) { issue((it + 1) & 1, (it + 1) * 32); cp_commit(); }

        char* s = sm + (it & 1) * STAGE_P;
        const __nv_bfloat16* Ahs = (const __nv_bfloat16*)s;
        const __nv_bfloat16* Als = Ahs + 128 * PA;
        const __nv_bfloat16* Bhs = (const __nv_bfloat16*)(s + 2 * A_BYTES);
        const __nv_bfloat16* Bls = Bhs + 32 * PB;

        #pragma unroll
        for (int ks = 0; ks < 2; ks++) {
            uint32_t ah[4][4], al_[4][4];
            #pragma unroll
            for (int mt = 0; mt < 4; mt++) {
                int row = wm * 64 + mt * 16 + (lane & 15);
                int col = ks * 16 + (lane >> 4) * 8;
                ldsm4(ah[mt][0],  ah[mt][1],  ah[mt][2],  ah[mt][3],
                      smem_u32(&Ahs[row * PA + col]));
                ldsm4(al_[mt][0], al_[mt][1], al_[mt][2], al_[mt][3],
                      smem_u32(&Als[row * PA + col]));
            }
            const int g = lane >> 3;
            #pragma unroll
            for (int p = 0; p < 2; p++) {
                int row = ks * 16 + (g & 1) * 8 + (lane & 7);
                int col = wn * 32 + p * 16 + (g >> 1) * 8;
                uint32_t h0, h1, h2, h3, l0, l1, l2, l3;
                ldsm4t(h0, h1, h2, h3, smem_u32(&Bhs[row * PB + col]));
                ldsm4t(l0, l1, l2, l3, smem_u32(&Bls[row * PB + col]));
                uint32_t bh0[2] = {h0, h1}, bh1[2] = {h2, h3};
                uint32_t bl0[2] = {l0, l1}, bl1[2] = {l2, l3};
                #pragma unroll
                for (int mt = 0; mt < 4; mt++) {
                    mma16816(acc[mt][2 * p],     ah[mt],  bh0);
                    mma16816(acc[mt][2 * p],     ah[mt],  bl0);
                    mma16816(acc[mt][2 * p],     al_[mt], bh0);
                    mma16816(acc[mt][2 * p + 1], ah[mt],  bh1);
                    mma16816(acc[mt][2 * p + 1], ah[mt],  bl1);
                    mma16816(acc[mt][2 * p + 1], al_[mt], bh1);
                }
            }
        }
    }

    // Epilogue
    const int r  = lane >> 2;
    const int cp = (lane & 3) * 2;
    #pragma unroll
    for (int nt = 0; nt < 4; nt++) {
        int col = n0 + wn * 32 + nt * 8 + cp;
        float2 bb = *(const float2*)(Bp + col);
        #pragma unroll
        for (int mt = 0; mt < 4; mt++) {
            #pragma unroll
            for (int half = 0; half < 2; half++) {
                int row = m0 + wm * 64 + mt * 16 + r + half * 8;
                float vx = acc[mt][nt][half * 2 + 0] + bb.x;
                float vy = acc[mt][nt][half * 2 + 1] + bb.y;
                if (mode == 0) {
                    __nv_bfloat16* Oh = (z == 0) ? g_Qh : (z == 1) ? g_Kh2 : g_Vh2;
                    __nv_bfloat16* Ol = (z == 0) ? g_Ql : (z == 1) ? g_Kl2 : g_Vl2;
                    int s = row >> 1, b = row & 1;
                    int hh = col >> 6, dh = col & 63;
                    size_t idx = ((size_t)(b * NHEAD + hh) * SLEN + s) * DHEAD + dh;
                    uint32_t hp, lp;
                    hilo_pack(vx, vy, hp, lp);
                    *(uint32_t*)(Oh + idx) = hp;
                    *(uint32_t*)(Ol + idx) = lp;
                } else {
                    *(float2*)(out_final + (size_t)row * DMODEL + col) =
                        make_float2(vx, vy);
                }
            }
        }
    }
}

// ---------------------------------------------------------------------------
// Causal flash attention, split-bf16 MMA, cp.async 2-stage K/V pipeline.
// BM=128 (8 warps x 16 rows, warp spans full N=64 -> warp-local softmax).
// ---------------------------------------------------------------------------
#define PK 72
#define KT_BYTES (64 * PK * 2)      // 9216
#define STAGE_A (4 * KT_BYTES)      // 36864: [Kh][Kl][Vh][Vl]

__global__ __launch_bounds__(256, 1) void attn_mma_kernel()
{
    extern __shared__ char sm[];
    const int tid  = threadIdx.x;
    const int lane = tid & 31;
    const int wid  = tid >> 5;
    const int qb   = gridDim.x - 1 - blockIdx.x;   // heavy blocks first
    const int bh   = blockIdx.y;
    const int b    = bh >> 4;
    const int h    = bh & 15;

    const __nv_bfloat16* Qgh = g_Qh  + (size_t)bh * SLEN * DHEAD;
    const __nv_bfloat16* Qgl = g_Ql  + (size_t)bh * SLEN * DHEAD;
    const __nv_bfloat16* Kgh = g_Kh2 + (size_t)bh * SLEN * DHEAD;
    const __nv_bfloat16* Kgl = g_Kl2 + (size_t)bh * SLEN * DHEAD;
    const __nv_bfloat16* Vgh = g_Vh2 + (size_t)bh * SLEN * DHEAD;
    const __nv_bfloat16* Vgl = g_Vl2 + (size_t)bh * SLEN * DHEAD;

    const int r  = lane >> 2;
    const int cp = (lane & 3) * 2;
    const int q0 = qb * 128 + wid * 16;

    const int l_row = tid >> 2, l_bc = (tid & 3) * 2;

    auto issueKV = [&](int stg, int kb) {
        char* s = sm + stg * STAGE_A;
        size_t gro = (size_t)(kb * 64 + l_row) * DHEAD;
        #pragma unroll
        for (int j = 0; j < 2; j++) {
            int ch = l_bc + j;
            uint32_t sa = smem_u32(s + l_row * 144 + ch * 16);
            cp16(sa,                Kgh + gro + ch * 8);
            cp16(sa + KT_BYTES,     Kgl + gro + ch * 8);
            cp16(sa + 2 * KT_BYTES, Vgh + gro + ch * 8);
            cp16(sa + 3 * KT_BYTES, Vgl + gro + ch * 8);
        }
    };

    // Q fragments (hi/lo) straight from global bf16
    uint32_t aqh[4][4], aql[4][4];
    #pragma unroll
    for (int ks = 0; ks < 4; ks++) {
        size_t r0o = (size_t)(q0 + r)     * DHEAD + ks * 16 + cp;
        size_t r1o = (size_t)(q0 + 8 + r) * DHEAD + ks * 16 + cp;
        aqh[ks][0] = *(const uint32_t*)(Qgh + r0o);
        aql[ks][0] = *(const uint32_t*)(Qgl + r0o);
        aqh[ks][1] = *(const uint32_t*)(Qgh + r1o);
        aql[ks][1] = *(const uint32_t*)(Qgl + r1o);
        aqh[ks][2] = *(const uint32_t*)(Qgh + r0o + 8);
        aql[ks][2] = *(const uint32_t*)(Qgl + r0o + 8);
        aqh[ks][3] = *(const uint32_t*)(Qgh + r1o + 8);
        aql[ks][3] = *(const uint32_t*)(Qgl + r1o + 8);
    }

    float o[8][4];
    #pragma unroll
    for (int t = 0; t < 8; t++)
        #pragma unroll
        for (int i = 0; i < 4; i++) o[t][i] = 0.f;
    float mrow[2] = {-1e30f, -1e30f};
    float lrow[2] = {0.f, 0.f};

    const int nkb = 2 * qb + 2;
    issueKV(0, 0);
    cp_commit();

    for (int kb = 0; kb < nkb; kb++) {
        cp_wait0();
        __syncthreads();
        if (kb + 1 < nkb) { issueKV((kb + 1) & 1, kb + 1); cp_commit(); }

        char* sb = sm + (kb & 1) * STAGE_A;
        const __nv_bfloat16* Khs = (const __nv_bfloat16*)sb;
        const __nv_bfloat16* Kls = (const __nv_bfloat16*)(sb + KT_BYTES);
        const __nv_bfloat16* Vhs = (const __nv_bfloat16*)(sb + 2 * KT_BYTES);
        const __nv_bfloat16* Vls = (const __nv_bfloat16*)(sb + 3 * KT_BYTES);

        // S = Q K^T
        float s[8][4];
        #pragma unroll
        for (int t = 0; t < 8; t++)
            #pragma unroll
            for (int i = 0; i < 4; i++) s[t][i] = 0.f;

        const int g = lane >> 3;
        #pragma unroll
        for (int ks = 0; ks < 4; ks++) {
            #pragma unroll
            for (int p = 0; p < 4; p++) {
                int row = p * 16 + (g >> 1) * 8 + (lane & 7);
                int col = ks * 16 + (g & 1) * 8;
                uint32_t h0, h1, h2, h3, l0, l1, l2, l3;
                ldsm4(h0, h1, h2, h3, smem_u32(&Khs[row * PK + col]));
                ldsm4(l0, l1, l2, l3, smem_u32(&Kls[row * PK + col]));
                uint32_t bh0[2] = {h0, h1}, bh1[2] = {h2, h3};
                uint32_t bl0[2] = {l0, l1}, bl1[2] = {l2, l3};
                mma16816(s[2 * p],     aqh[ks], bh0);
                mma16816(s[2 * p],     aqh[ks], bl0);
                mma16816(s[2 * p],     aql[ks], bh0);
                mma16816(s[2 * p + 1], aqh[ks], bh1);
                mma16816(s[2 * p + 1], aqh[ks], bl1);
                mma16816(s[2 * p + 1], aql[ks], bh1);
            }
        }

        #pragma unroll
        for (int t = 0; t < 8; t++)
            #pragma unroll
            for (int i = 0; i < 4; i++) s[t][i] *= 0.125f;   // 1/sqrt(64)

        if (kb >= 2 * qb) {   // causal diagonal region
            #pragma unroll
            for (int t = 0; t < 8; t++)
                #pragma unroll
                for (int i = 0; i < 4; i++) {
                    int jg = kb * 64 + t * 8 + cp + (i & 1);
                    int qg = q0 + r + (i >> 1) * 8;
                    if (jg > qg) s[t][i] = -1e30f;
                }
        }

        // Online softmax per half-row
        #pragma unroll
        for (int hr = 0; hr < 2; hr++) {
            float rm = -1e30f;
            #pragma unroll
            for (int t = 0; t < 8; t++)
                rm = fmaxf(rm, fmaxf(s[t][hr * 2], s[t][hr * 2 + 1]));
            rm = fmaxf(rm, __shfl_xor_sync(0xffffffffu, rm, 1));
            rm = fmaxf(rm, __shfl_xor_sync(0xffffffffu, rm, 2));
            float mn = fmaxf(mrow[hr], rm);
            float alpha = __expf(mrow[hr] - mn);
            mrow[hr] = mn;
            float rs = 0.f;
            #pragma unroll
            for (int t = 0; t < 8; t++) {
                s[t][hr * 2]     = __expf(s[t][hr * 2] - mn);
                s[t][hr * 2 + 1] = __expf(s[t][hr * 2 + 1] - mn);
                rs += s[t][hr * 2] + s[t][hr * 2 + 1];
            }
            rs += __shfl_xor_sync(0xffffffffu, rs, 1);
            rs += __shfl_xor_sync(0xffffffffu, rs, 2);
            lrow[hr] = lrow[hr] * alpha + rs;
            #pragma unroll
            for (int t = 0; t < 8; t++) {
                o[t][hr * 2]     *= alpha;
                o[t][hr * 2 + 1] *= alpha;
            }
        }

        // O += P V
        #pragma unroll
        for (int ks = 0; ks < 4; ks++) {
            uint32_t pah[4], pal[4];
            hilo_pack(s[2 * ks][0],     s[2 * ks][1],     pah[0], pal[0]);
            hilo_pack(s[2 * ks][2],     s[2 * ks][3],     pah[1], pal[1]);
            hilo_pack(s[2 * ks + 1][0], s[2 * ks + 1][1], pah[2], pal[2]);
            hilo_pack(s[2 * ks + 1][2], s[2 * ks + 1][3], pah[3], pal[3]);
            #pragma unroll
            for (int p = 0; p < 4; p++) {
                int row = ks * 16 + (g & 1) * 8 + (lane & 7);
                int col = p * 16 + (g >> 1) * 8;
                uint32_t h0, h1, h2, h3, l0, l1, l2, l3;
                ldsm4t(h0, h1, h2, h3, smem_u32(&Vhs[row * PK + col]));
                ldsm4t(l0, l1, l2, l3, smem_u32(&Vls[row * PK + col]));
                uint32_t bh0[2] = {h0, h1}, bh1[2] = {h2, h3};
                uint32_t bl0[2] = {l0, l1}, bl1[2] = {l2, l3};
                mma16816(o[2 * p],     pah, bh0);
                mma16816(o[2 * p],     pah, bl0);
                mma16816(o[2 * p],     pal, bh0);
                mma16816(o[2 * p + 1], pah, bh1);
                mma16816(o[2 * p + 1], pah, bl1);
                mma16816(o[2 * p + 1], pal, bh1);
            }
        }
    }

    // Normalize; write hi/lo bf16 to attention-output buffer (S, B, D)
    float inv0 = 1.f / lrow[0];
    float inv1 = 1.f / lrow[1];
    #pragma unroll
    for (int t = 0; t < 8; t++) {
        int d = t * 8 + cp;
        int s0 = q0 + r, s1 = q0 + 8 + r;
        size_t i0 = ((size_t)s0 * BATCH + b) * DMODEL + h * DHEAD + d;
        size_t i1 = ((size_t)s1 * BATCH + b) * DMODEL + h * DHEAD + d;
        uint32_t hp, lp;
        hilo_pack(o[t][0] * inv0, o[t][1] * inv0, hp, lp);
        *(uint32_t*)(g_Ah + i0) = hp;
        *(uint32_t*)(g_Al + i0) = lp;
        hilo_pack(o[t][2] * inv1, o[t][3] * inv1, hp, lp);
        *(uint32_t*)(g_Ah + i1) = hp;
        *(uint32_t*)(g_Al + i1) = lp;
    }
}

// ---------------------------------------------------------------------------
// Inputs (metadata order): query, key, value, mask, Wq, bq, Wk, bk, Wv, bv,
// Wo, bo. mask is the fixed causal tril -> handled analytically, not read.
// ---------------------------------------------------------------------------
extern "C" void kernel_launch(void* const* d_in, const int* in_sizes, int n_in,
                              void* d_out, int out_size)
{
    (void)in_sizes; (void)n_in; (void)out_size;
    const float* query = (const float*)d_in[0];
    const float* key   = (const float*)d_in[1];
    const float* value = (const float*)d_in[2];
    const float* Wq = (const float*)d_in[4];
    const float* bq = (const float*)d_in[5];
    const float* Wk = (const float*)d_in[6];
    const float* bk = (const float*)d_in[7];
    const float* Wv = (const float*)d_in[8];
    const float* bv = (const float*)d_in[9];
    const float* Wo = (const float*)d_in[10];
    const float* bo = (const float*)d_in[11];
    float* out = (float*)d_out;

    static bool attr_set = false;
    if (!attr_set) {
        cudaFuncSetAttribute(proj_mma_kernel,
                             cudaFuncAttributeMaxDynamicSharedMemorySize, 2 * STAGE_P);
        cudaFuncSetAttribute(attn_mma_kernel,
                             cudaFuncAttributeMaxDynamicSharedMemorySize, 2 * STAGE_A);
        attr_set = true;
    }

    dim3 blk(256);
    convert_kernel<<<dim3(4096, 1, 7), blk>>>(query, key, value, Wq, Wk, Wv, Wo);
    proj_mma_kernel<<<dim3(8, 32, 3), blk, 2 * STAGE_P>>>(bq, bk, bv, nullptr, 0);
    attn_mma_kernel<<<dim3(16, 32), blk, 2 * STAGE_A>>>();
    proj_mma_kernel<<<dim3(8, 32, 1), blk, 2 * STAGE_P>>>(bo, nullptr, nullptr, out, 1);
}

// round 8
// speedup vs baseline: 2.6165x; 1.0690x over previous
#include <cuda_runtime.h>
#include <cuda_bf16.h>
#include <math.h>
#include <stdint.h>

#define SLEN   2048
#define BATCH  2
#define DMODEL 1024
#define NHEAD  16
#define DHEAD  64
#define NX ((size_t)SLEN * BATCH * DMODEL)   // 4194304
#define NW ((size_t)DMODEL * DMODEL)         // 1048576

// bf16 hi/lo copies of everything (allocation-free rule: __device__ globals)
static __device__ __nv_bfloat16 g_Xh[3][NX], g_Xl[3][NX];   // query,key,value
static __device__ __nv_bfloat16 g_Wh[4][NW], g_Wl[4][NW];   // Wq,Wk,Wv,Wo
static __device__ __nv_bfloat16 g_Qh[NX], g_Ql[NX];         // (B,H,S,DH)
static __device__ __nv_bfloat16 g_Kh2[NX], g_Kl2[NX];
static __device__ __nv_bfloat16 g_Vh2[NX], g_Vl2[NX];
static __device__ __nv_bfloat16 g_Ah[NX], g_Al[NX];         // attn out (S,B,D)

// ---------------------------------------------------------------------------
// Helpers
// ---------------------------------------------------------------------------
__device__ __forceinline__ uint32_t smem_u32(const void* p) {
    return (uint32_t)__cvta_generic_to_shared(p);
}
__device__ __forceinline__ void cp16(uint32_t s, const void* g) {
    asm volatile("cp.async.cg.shared.global [%0], [%1], 16;" :: "r"(s), "l"(g));
}
__device__ __forceinline__ void cp_commit() {
    asm volatile("cp.async.commit_group;");
}
__device__ __forceinline__ void cp_wait0() {
    asm volatile("cp.async.wait_group 0;" ::: "memory");
}
__device__ __forceinline__ void ldsm4(uint32_t& r0, uint32_t& r1, uint32_t& r2,
                                      uint32_t& r3, uint32_t a) {
    asm volatile("ldmatrix.sync.aligned.m8n8.x4.shared.b16 {%0,%1,%2,%3}, [%4];"
                 : "=r"(r0), "=r"(r1), "=r"(r2), "=r"(r3) : "r"(a));
}
__device__ __forceinline__ void ldsm4t(uint32_t& r0, uint32_t& r1, uint32_t& r2,
                                       uint32_t& r3, uint32_t a) {
    asm volatile("ldmatrix.sync.aligned.m8n8.x4.trans.shared.b16 {%0,%1,%2,%3}, [%4];"
                 : "=r"(r0), "=r"(r1), "=r"(r2), "=r"(r3) : "r"(a));
}
__device__ __forceinline__ void mma16816(float* d, const uint32_t* a, const uint32_t* b) {
    asm volatile("mma.sync.aligned.m16n8k16.row.col.f32.bf16.bf16.f32 "
                 "{%0,%1,%2,%3}, {%4,%5,%6,%7}, {%8,%9}, {%0,%1,%2,%3};"
                 : "+f"(d[0]), "+f"(d[1]), "+f"(d[2]), "+f"(d[3])
                 : "r"(a[0]), "r"(a[1]), "r"(a[2]), "r"(a[3]), "r"(b[0]), "r"(b[1]));
}
__device__ __forceinline__ void hilo_pack(float x, float y, uint32_t& h, uint32_t& l) {
    __nv_bfloat16 hx = __float2bfloat16(x);
    __nv_bfloat16 hy = __float2bfloat16(y);
    __nv_bfloat16 lx = __float2bfloat16(x - __bfloat162float(hx));
    __nv_bfloat16 ly = __float2bfloat16(y - __bfloat162float(hy));
    __nv_bfloat162 hp = __halves2bfloat162(hx, hy);
    __nv_bfloat162 lp = __halves2bfloat162(lx, ly);
    h = *reinterpret_cast<uint32_t*>(&hp);
    l = *reinterpret_cast<uint32_t*>(&lp);
}

// ---------------------------------------------------------------------------
// Prepass: fp32 -> hi/lo bf16 for the 3 inputs and 4 weights
// ---------------------------------------------------------------------------
__global__ __launch_bounds__(256) void convert_kernel(
    const float* __restrict__ q, const float* __restrict__ k, const float* __restrict__ v,
    const float* __restrict__ wq, const float* __restrict__ wk,
    const float* __restrict__ wv, const float* __restrict__ wo)
{
    const int z = blockIdx.z;
    const float* src;
    __nv_bfloat16 *dh, *dl;
    size_t n;
    switch (z) {
        case 0: src = q;  dh = g_Xh[0]; dl = g_Xl[0]; n = NX; break;
        case 1: src = k;  dh = g_Xh[1]; dl = g_Xl[1]; n = NX; break;
        case 2: src = v;  dh = g_Xh[2]; dl = g_Xl[2]; n = NX; break;
        case 3: src = wq; dh = g_Wh[0]; dl = g_Wl[0]; n = NW; break;
        case 4: src = wk; dh = g_Wh[1]; dl = g_Wl[1]; n = NW; break;
        case 5: src = wv; dh = g_Wh[2]; dl = g_Wl[2]; n = NW; break;
        default: src = wo; dh = g_Wh[3]; dl = g_Wl[3]; n = NW; break;
    }
    size_t i = ((size_t)blockIdx.x * 256 + threadIdx.x) * 4;
    if (i >= n) return;
    float4 val = *(const float4*)(src + i);
    uint32_t h0, l0, h1, l1;
    hilo_pack(val.x, val.y, h0, l0);
    hilo_pack(val.z, val.w, h1, l1);
    *(uint2*)(dh + i) = make_uint2(h0, h1);
    *(uint2*)(dl + i) = make_uint2(l0, l1);
}

// ---------------------------------------------------------------------------
// Projection GEMM: C[4096,1024] = X @ W + bias, 3-pass split-bf16 MMA.
// bf16 hi/lo inputs from globals; cp.async 2-stage pipeline; 1 barrier/iter.
// NOW 2 CTAs/SM (launch_bounds(256,2)): fills tensor-pipe dependency bubbles.
// mode 0: z picks q/k/v; writes hi/lo bf16 scattered to (B,H,S,DH).
// mode 1: g_A @ Wo + bo -> fp32 out.
// ---------------------------------------------------------------------------
#define PA 40
#define PB 136
#define A_BYTES (128 * PA * 2)                 // 10240
#define B_BYTES (32 * PB * 2)                  // 8704
#define STAGE_P (2 * A_BYTES + 2 * B_BYTES)    // 37888

__global__ __launch_bounds__(256, 2) void proj_mma_kernel(
    const float* __restrict__ Bias0, const float* __restrict__ Bias1,
    const float* __restrict__ Bias2, float* __restrict__ out_final, int mode)
{
    extern __shared__ char sm[];
    const int tid  = threadIdx.x;
    const int lane = tid & 31;
    const int wid  = tid >> 5;
    const int wm   = wid >> 2;
    const int wn   = wid & 3;
    const int z    = blockIdx.z;

    const __nv_bfloat16 *Agh, *Agl, *Wgh, *Wgl;
    const float* Bp;
    if (mode == 0) {
        Agh = g_Xh[z]; Agl = g_Xl[z]; Wgh = g_Wh[z]; Wgl = g_Wl[z];
        Bp = (z == 0) ? Bias0 : (z == 1) ? Bias1 : Bias2;
    } else {
        Agh = g_Ah; Agl = g_Al; Wgh = g_Wh[3]; Wgl = g_Wl[3];
        Bp = Bias0;
    }

    const int m0 = blockIdx.y * 128;
    const int n0 = blockIdx.x * 128;

    const int a_row = tid >> 1, a_bc = (tid & 1) * 2;
    const int b_row = tid >> 3, b_bc = (tid & 7) * 2;

    auto issue = [&](int stg, int k0) {
        char* s = sm + stg * STAGE_P;
        #pragma unroll
        for (int j = 0; j < 2; j++) {
            int ch = a_bc + j;
            uint32_t sa = smem_u32(s + a_row * 80 + ch * 16);
            const __nv_bfloat16* gh = Agh + (size_t)(m0 + a_row) * DMODEL + k0 + ch * 8;
            const __nv_bfloat16* gl = Agl + (size_t)(m0 + a_row) * DMODEL + k0 + ch * 8;
            cp16(sa, gh);
            cp16(sa + A_BYTES, gl);
        }
        #pragma unroll
        for (int j = 0; j < 2; j++) {
            int ch = b_bc + j;
            uint32_t sb = smem_u32(s + 2 * A_BYTES + b_row * 272 + ch * 16);
            const __nv_bfloat16* gh = Wgh + (size_t)(k0 + b_row) * DMODEL + n0 + ch * 8;
            const __nv_bfloat16* gl = Wgl + (size_t)(k0 + b_row) * DMODEL + n0 + ch * 8;
            cp16(sb, gh);
            cp16(sb + B_BYTES, gl);
        }
    };

    float acc[4][4][4];
    #pragma unroll
    for (int mt = 0; mt < 4; mt++)
        #pragma unroll
        for (int nt = 0; nt < 4; nt++)
            #pragma unroll
            for (int i = 0; i < 4; i++) acc[mt][nt][i] = 0.f;

    issue(0, 0);
    cp_commit();

    for (int it = 0; it < DMODEL / 32; it++) {
        cp_wait0();
        __syncthreads();
        if (it + 1 < DMODEL / 32) { issue((it + 1) & 1, (it + 1) * 32); cp_commit(); }

        char* s = sm + (it & 1) * STAGE_P;
        const __nv_bfloat16* Ahs = (const __nv_bfloat16*)s;
        const __nv_bfloat16* Als = Ahs + 128 * PA;
        const __nv_bfloat16* Bhs = (const __nv_bfloat16*)(s + 2 * A_BYTES);
        const __nv_bfloat16* Bls = Bhs + 32 * PB;

        #pragma unroll
        for (int ks = 0; ks < 2; ks++) {
            uint32_t ah[4][4], al_[4][4];
            #pragma unroll
            for (int mt = 0; mt < 4; mt++) {
                int row = wm * 64 + mt * 16 + (lane & 15);
                int col = ks * 16 + (lane >> 4) * 8;
                ldsm4(ah[mt][0],  ah[mt][1],  ah[mt][2],  ah[mt][3],
                      smem_u32(&Ahs[row * PA + col]));
                ldsm4(al_[mt][0], al_[mt][1], al_[mt][2], al_[mt][3],
                      smem_u32(&Als[row * PA + col]));
            }
            const int g = lane >> 3;
            #pragma unroll
            for (int p = 0; p < 2; p++) {
                int row = ks * 16 + (g & 1) * 8 + (lane & 7);
                int col = wn * 32 + p * 16 + (g >> 1) * 8;
                uint32_t h0, h1, h2, h3, l0, l1, l2, l3;
                ldsm4t(h0, h1, h2, h3, smem_u32(&Bhs[row * PB + col]));
                ldsm4t(l0, l1, l2, l3, smem_u32(&Bls[row * PB + col]));
                uint32_t bh0[2] = {h0, h1}, bh1[2] = {h2, h3};
                uint32_t bl0[2] = {l0, l1}, bl1[2] = {l2, l3};
                #pragma unroll
                for (int mt = 0; mt < 4; mt++) {
                    mma16816(acc[mt][2 * p],     ah[mt],  bh0);
                    mma16816(acc[mt][2 * p],     ah[mt],  bl0);
                    mma16816(acc[mt][2 * p],     al_[mt], bh0);
                    mma16816(acc[mt][2 * p + 1], ah[mt],  bh1);
                    mma16816(acc[mt][2 * p + 1], ah[mt],  bl1);
                    mma16816(acc[mt][2 * p + 1], al_[mt], bh1);
                }
            }
        }
    }

    // Epilogue
    const int r  = lane >> 2;
    const int cp = (lane & 3) * 2;
    #pragma unroll
    for (int nt = 0; nt < 4; nt++) {
        int col = n0 + wn * 32 + nt * 8 + cp;
        float2 bb = *(const float2*)(Bp + col);
        #pragma unroll
        for (int mt = 0; mt < 4; mt++) {
            #pragma unroll
            for (int half = 0; half < 2; half++) {
                int row = m0 + wm * 64 + mt * 16 + r + half * 8;
                float vx = acc[mt][nt][half * 2 + 0] + bb.x;
                float vy = acc[mt][nt][half * 2 + 1] + bb.y;
                if (mode == 0) {
                    __nv_bfloat16* Oh = (z == 0) ? g_Qh : (z == 1) ? g_Kh2 : g_Vh2;
                    __nv_bfloat16* Ol = (z == 0) ? g_Ql : (z == 1) ? g_Kl2 : g_Vl2;
                    int s = row >> 1, b = row & 1;
                    int hh = col >> 6, dh = col & 63;
                    size_t idx = ((size_t)(b * NHEAD + hh) * SLEN + s) * DHEAD + dh;
                    uint32_t hp, lp;
                    hilo_pack(vx, vy, hp, lp);
                    *(uint32_t*)(Oh + idx) = hp;
                    *(uint32_t*)(Ol + idx) = lp;
                } else {
                    *(float2*)(out_final + (size_t)row * DMODEL + col) =
                        make_float2(vx, vy);
                }
            }
        }
    }
}

// ---------------------------------------------------------------------------
// Causal flash attention, split-bf16 MMA, cp.async 2-stage K/V pipeline.
// BM=128 (8 warps x 16 rows, warp spans full N=64 -> warp-local softmax).
// NOW 2 CTAs/SM (launch_bounds(256,2)).
// ---------------------------------------------------------------------------
#define PK 72
#define KT_BYTES (64 * PK * 2)      // 9216
#define STAGE_A (4 * KT_BYTES)      // 36864: [Kh][Kl][Vh][Vl]

__global__ __launch_bounds__(256, 2) void attn_mma_kernel()
{
    extern __shared__ char sm[];
    const int tid  = threadIdx.x;
    const int lane = tid & 31;
    const int wid  = tid >> 5;
    const int qb   = gridDim.x - 1 - blockIdx.x;   // heavy blocks first
    const int bh   = blockIdx.y;
    const int b    = bh >> 4;
    const int h    = bh & 15;

    const __nv_bfloat16* Qgh = g_Qh  + (size_t)bh * SLEN * DHEAD;
    const __nv_bfloat16* Qgl = g_Ql  + (size_t)bh * SLEN * DHEAD;
    const __nv_bfloat16* Kgh = g_Kh2 + (size_t)bh * SLEN * DHEAD;
    const __nv_bfloat16* Kgl = g_Kl2 + (size_t)bh * SLEN * DHEAD;
    const __nv_bfloat16* Vgh = g_Vh2 + (size_t)bh * SLEN * DHEAD;
    const __nv_bfloat16* Vgl = g_Vl2 + (size_t)bh * SLEN * DHEAD;

    const int r  = lane >> 2;
    const int cp = (lane & 3) * 2;
    const int q0 = qb * 128 + wid * 16;

    const int l_row = tid >> 2, l_bc = (tid & 3) * 2;

    auto issueKV = [&](int stg, int kb) {
        char* s = sm + stg * STAGE_A;
        size_t gro = (size_t)(kb * 64 + l_row) * DHEAD;
        #pragma unroll
        for (int j = 0; j < 2; j++) {
            int ch = l_bc + j;
            uint32_t sa = smem_u32(s + l_row * 144 + ch * 16);
            cp16(sa,                Kgh + gro + ch * 8);
            cp16(sa + KT_BYTES,     Kgl + gro + ch * 8);
            cp16(sa + 2 * KT_BYTES, Vgh + gro + ch * 8);
            cp16(sa + 3 * KT_BYTES, Vgl + gro + ch * 8);
        }
    };

    uint32_t aqh[4][4], aql[4][4];
    #pragma unroll
    for (int ks = 0; ks < 4; ks++) {
        size_t r0o = (size_t)(q0 + r)     * DHEAD + ks * 16 + cp;
        size_t r1o = (size_t)(q0 + 8 + r) * DHEAD + ks * 16 + cp;
        aqh[ks][0] = *(const uint32_t*)(Qgh + r0o);
        aql[ks][0] = *(const uint32_t*)(Qgl + r0o);
        aqh[ks][1] = *(const uint32_t*)(Qgh + r1o);
        aql[ks][1] = *(const uint32_t*)(Qgl + r1o);
        aqh[ks][2] = *(const uint32_t*)(Qgh + r0o + 8);
        aql[ks][2] = *(const uint32_t*)(Qgl + r0o + 8);
        aqh[ks][3] = *(const uint32_t*)(Qgh + r1o + 8);
        aql[ks][3] = *(const uint32_t*)(Qgl + r1o + 8);
    }

    float o[8][4];
    #pragma unroll
    for (int t = 0; t < 8; t++)
        #pragma unroll
        for (int i = 0; i < 4; i++) o[t][i] = 0.f;
    float mrow[2] = {-1e30f, -1e30f};
    float lrow[2] = {0.f, 0.f};

    const int nkb = 2 * qb + 2;
    issueKV(0, 0);
    cp_commit();

    for (int kb = 0; kb < nkb; kb++) {
        cp_wait0();
        __syncthreads();
        if (kb + 1 < nkb) { issueKV((kb + 1) & 1, kb + 1); cp_commit(); }

        char* sbk = sm + (kb & 1) * STAGE_A;
        const __nv_bfloat16* Khs = (const __nv_bfloat16*)sbk;
        const __nv_bfloat16* Kls = (const __nv_bfloat16*)(sbk + KT_BYTES);
        const __nv_bfloat16* Vhs = (const __nv_bfloat16*)(sbk + 2 * KT_BYTES);
        const __nv_bfloat16* Vls = (const __nv_bfloat16*)(sbk + 3 * KT_BYTES);

        float s[8][4];
        #pragma unroll
        for (int t = 0; t < 8; t++)
            #pragma unroll
            for (int i = 0; i < 4; i++) s[t][i] = 0.f;

        const int g = lane >> 3;
        #pragma unroll
        for (int ks = 0; ks < 4; ks++) {
            #pragma unroll
            for (int p = 0; p < 4; p++) {
                int row = p * 16 + (g >> 1) * 8 + (lane & 7);
                int col = ks * 16 + (g & 1) * 8;
                uint32_t h0, h1, h2, h3, l0, l1, l2, l3;
                ldsm4(h0, h1, h2, h3, smem_u32(&Khs[row * PK + col]));
                ldsm4(l0, l1, l2, l3, smem_u32(&Kls[row * PK + col]));
                uint32_t bh0[2] = {h0, h1}, bh1[2] = {h2, h3};
                uint32_t bl0[2] = {l0, l1}, bl1[2] = {l2, l3};
                mma16816(s[2 * p],     aqh[ks], bh0);
                mma16816(s[2 * p],     aqh[ks], bl0);
                mma16816(s[2 * p],     aql[ks], bh0);
                mma16816(s[2 * p + 1], aqh[ks], bh1);
                mma16816(s[2 * p + 1], aqh[ks], bl1);
                mma16816(s[2 * p + 1], aql[ks], bh1);
            }
        }

        #pragma unroll
        for (int t = 0; t < 8; t++)
            #pragma unroll
            for (int i = 0; i < 4; i++) s[t][i] *= 0.125f;   // 1/sqrt(64)

        if (kb >= 2 * qb) {   // causal diagonal region
            #pragma unroll
            for (int t = 0; t < 8; t++)
                #pragma unroll
                for (int i = 0; i < 4; i++) {
                    int jg = kb * 64 + t * 8 + cp + (i & 1);
                    int qg = q0 + r + (i >> 1) * 8;
                    if (jg > qg) s[t][i] = -1e30f;
                }
        }

        // Online softmax per half-row
        #pragma unroll
        for (int hr = 0; hr < 2; hr++) {
            float rm = -1e30f;
            #pragma unroll
            for (int t = 0; t < 8; t++)
                rm = fmaxf(rm, fmaxf(s[t][hr * 2], s[t][hr * 2 + 1]));
            rm = fmaxf(rm, __shfl_xor_sync(0xffffffffu, rm, 1));
            rm = fmaxf(rm, __shfl_xor_sync(0xffffffffu, rm, 2));
            float mn = fmaxf(mrow[hr], rm);
            float alpha = __expf(mrow[hr] - mn);
            mrow[hr] = mn;
            float rs = 0.f;
            #pragma unroll
            for (int t = 0; t < 8; t++) {
                s[t][hr * 2]     = __expf(s[t][hr * 2] - mn);
                s[t][hr * 2 + 1] = __expf(s[t][hr * 2 + 1] - mn);
                rs += s[t][hr * 2] + s[t][hr * 2 + 1];
            }
            rs += __shfl_xor_sync(0xffffffffu, rs, 1);
            rs += __shfl_xor_sync(0xffffffffu, rs, 2);
            lrow[hr] = lrow[hr] * alpha + rs;
            #pragma unroll
            for (int t = 0; t < 8; t++) {
                o[t][hr * 2]     *= alpha;
                o[t][hr * 2 + 1] *= alpha;
            }
        }

        // O += P V
        #pragma unroll
        for (int ks = 0; ks < 4; ks++) {
            uint32_t pah[4], pal[4];
            hilo_pack(s[2 * ks][0],     s[2 * ks][1],     pah[0], pal[0]);
            hilo_pack(s[2 * ks][2],     s[2 * ks][3],     pah[1], pal[1]);
            hilo_pack(s[2 * ks + 1][0], s[2 * ks + 1][1], pah[2], pal[2]);
            hilo_pack(s[2 * ks + 1][2], s[2 * ks + 1][3], pah[3], pal[3]);
            #pragma unroll
            for (int p = 0; p < 4; p++) {
                int row = ks * 16 + (g & 1) * 8 + (lane & 7);
                int col = p * 16 + (g >> 1) * 8;
                uint32_t h0, h1, h2, h3, l0, l1, l2, l3;
                ldsm4t(h0, h1, h2, h3, smem_u32(&Vhs[row * PK + col]));
                ldsm4t(l0, l1, l2, l3, smem_u32(&Vls[row * PK + col]));
                uint32_t bh0[2] = {h0, h1}, bh1[2] = {h2, h3};
                uint32_t bl0[2] = {l0, l1}, bl1[2] = {l2, l3};
                mma16816(o[2 * p],     pah, bh0);
                mma16816(o[2 * p],     pah, bl0);
                mma16816(o[2 * p],     pal, bh0);
                mma16816(o[2 * p + 1], pah, bh1);
                mma16816(o[2 * p + 1], pah, bl1);
                mma16816(o[2 * p + 1], pal, bh1);
            }
        }
    }

    // Normalize; write hi/lo bf16 to attention-output buffer (S, B, D)
    float inv0 = 1.f / lrow[0];
    float inv1 = 1.f / lrow[1];
    #pragma unroll
    for (int t = 0; t < 8; t++) {
        int d = t * 8 + cp;
        int s0 = q0 + r, s1 = q0 + 8 + r;
        size_t i0 = ((size_t)s0 * BATCH + b) * DMODEL + h * DHEAD + d;
        size_t i1 = ((size_t)s1 * BATCH + b) * DMODEL + h * DHEAD + d;
        uint32_t hp, lp;
        hilo_pack(o[t][0] * inv0, o[t][1] * inv0, hp, lp);
        *(uint32_t*)(g_Ah + i0) = hp;
        *(uint32_t*)(g_Al + i0) = lp;
        hilo_pack(o[t][2] * inv1, o[t][3] * inv1, hp, lp);
        *(uint32_t*)(g_Ah + i1) = hp;
        *(uint32_t*)(g_Al + i1) = lp;
    }
}

// ---------------------------------------------------------------------------
// Inputs (metadata order): query, key, value, mask, Wq, bq, Wk, bk, Wv, bv,
// Wo, bo. mask is the fixed causal tril -> handled analytically, not read.
// ---------------------------------------------------------------------------
extern "C" void kernel_launch(void* const* d_in, const int* in_sizes, int n_in,
                              void* d_out, int out_size)
{
    (void)in_sizes; (void)n_in; (void)out_size;
    const float* query = (const float*)d_in[0];
    const float* key   = (const float*)d_in[1];
    const float* value = (const float*)d_in[2];
    const float* Wq = (const float*)d_in[4];
    const float* bq = (const float*)d_in[5];
    const float* Wk = (const float*)d_in[6];
    const float* bk = (const float*)d_in[7];
    const float* Wv = (const float*)d_in[8];
    const float* bv = (const float*)d_in[9];
    const float* Wo = (const float*)d_in[10];
    const float* bo = (const float*)d_in[11];
    float* out = (float*)d_out;

    cudaFuncSetAttribute(proj_mma_kernel,
                         cudaFuncAttributeMaxDynamicSharedMemorySize, 2 * STAGE_P);
    cudaFuncSetAttribute(attn_mma_kernel,
                         cudaFuncAttributeMaxDynamicSharedMemorySize, 2 * STAGE_A);

    dim3 blk(256);
    convert_kernel<<<dim3(4096, 1, 7), blk>>>(query, key, value, Wq, Wk, Wv, Wo);
    proj_mma_kernel<<<dim3(8, 32, 3), blk, 2 * STAGE_P>>>(bq, bk, bv, nullptr, 0);
    attn_mma_kernel<<<dim3(16, 32), blk, 2 * STAGE_A>>>();
    proj_mma_kernel<<<dim3(8, 32, 1), blk, 2 * STAGE_P>>>(bo, nullptr, nullptr, out, 1);
}